// round 1
// baseline (speedup 1.0000x reference)
#include <cuda_runtime.h>
#include <math.h>

// MoE FFN: x[N,D] -> router top-2 of E -> grouped expert FFN (D->H gelu H->D) -> combine.
// N=4096, D=1024, H=4096, E=8 for this problem (dims derived at runtime, caps below).

#define MAXE      16
#define CAP_ROWS  8192          // N * TOP_K
#define CAP_H     4096
#define CAP_D     1024

__device__ int   g_cnt[MAXE];
__device__ int   g_off[MAXE];
__device__ int   g_cur[MAXE];
__device__ int   g_rows[CAP_ROWS];     // grouped list: token*2 + slot
__device__ int   g_tki[CAP_ROWS];      // per (token,slot): expert id
__device__ float g_tkw[CAP_ROWS];      // per (token,slot): routing weight
__device__ float g_hidden[(size_t)CAP_ROWS * CAP_H];  // 128 MB scratch
__device__ float g_ybuf[(size_t)CAP_ROWS * CAP_D];    // 32 MB scratch

// ---------------------------------------------------------------- init
__global__ void init_kernel(int E) {
    if (threadIdx.x < E) g_cnt[threadIdx.x] = 0;
}

// ---------------------------------------------------------------- router
// one block (128 threads) per token: logits = x_row @ gate_w, top-2, renorm.
__global__ __launch_bounds__(128) void router_kernel(
    const float* __restrict__ x, const float* __restrict__ gw,
    int D, int E)
{
    int n = blockIdx.x;
    int t = threadIdx.x;
    float acc[MAXE];
    #pragma unroll
    for (int e = 0; e < MAXE; e++) acc[e] = 0.f;

    const float* xr = x + (size_t)n * D;
    for (int i = t; i < D; i += 128) {
        float xv = xr[i];
        const float* g = gw + (size_t)i * E;
        for (int e = 0; e < E; e++) acc[e] += xv * g[e];
    }
    // warp reduce each logit
    for (int e = 0; e < E; e++)
        for (int o = 16; o > 0; o >>= 1)
            acc[e] += __shfl_down_sync(0xffffffffu, acc[e], o);

    __shared__ float sred[4][MAXE];
    int warp = t >> 5, lane = t & 31;
    if (lane == 0)
        for (int e = 0; e < E; e++) sred[warp][e] = acc[e];
    __syncthreads();

    if (t == 0) {
        float l[MAXE];
        for (int e = 0; e < E; e++)
            l[e] = sred[0][e] + sred[1][e] + sred[2][e] + sred[3][e];
        // top-2 (jax top_k: descending, ties -> lower index)
        int i0 = 0;
        for (int e = 1; e < E; e++) if (l[e] > l[i0]) i0 = e;
        int i1 = -1;
        for (int e = 0; e < E; e++) {
            if (e == i0) continue;
            if (i1 < 0 || l[e] > l[i1]) i1 = e;
        }
        // renormalized softmax over top-2 (full-softmax Z cancels)
        float e1 = expf(l[i1] - l[i0]);
        float s  = 1.0f + e1;
        g_tki[n * 2 + 0] = i0;  g_tkw[n * 2 + 0] = 1.0f / s;
        g_tki[n * 2 + 1] = i1;  g_tkw[n * 2 + 1] = e1 / s;
        atomicAdd(&g_cnt[i0], 1);
        atomicAdd(&g_cnt[i1], 1);
    }
}

// ---------------------------------------------------------------- scan
__global__ void scan_kernel(int E) {
    if (threadIdx.x == 0) {
        int off = 0;
        for (int e = 0; e < E; e++) {
            g_off[e] = off; g_cur[e] = off; off += g_cnt[e];
        }
    }
}

// ---------------------------------------------------------------- scatter
__global__ void scatter_kernel(int N) {
    int n = blockIdx.x * blockDim.x + threadIdx.x;
    if (n >= N) return;
    #pragma unroll
    for (int k = 0; k < 2; k++) {
        int e = g_tki[n * 2 + k];
        int p = atomicAdd(&g_cur[e], 1);
        g_rows[p] = n * 2 + k;
    }
}

// ---------------------------------------------------------------- grouped GEMM
// STAGE 1: hidden[p, :] = gelu( x[token(p), :] @ w1[e] + b1[e] )   K=D, NC=H
// STAGE 2: ybuf[rows(p), :] =  hidden[p, :] @ w2[e] + b2[e]        K=H, NC=D
// 128x128x16 tile, 256 threads, 8x8 per thread. M ragged per expert; NC,K
// are multiples of 128/16 for this problem.
template<int STAGE>
__global__ __launch_bounds__(256) void gemm_kernel(
    const float* __restrict__ Xin,     // x (stage1) / unused (stage2)
    const float* __restrict__ Ball,    // w1 or w2: [E, K, NC]
    const float* __restrict__ biasall, // [E, NC]
    int K, int NC)
{
    constexpr int BM = 128, BN = 128, BK = 16;
    int e   = blockIdx.z;
    int cnt = g_cnt[e];
    int m0  = blockIdx.y * BM;
    if (m0 >= cnt) return;
    int off = g_off[e];
    int n0  = blockIdx.x * BN;
    const float* B    = Ball    + (size_t)e * K * NC + n0;
    const float* bias = biasall + (size_t)e * NC + n0;

    __shared__ float As[BK][BM];
    __shared__ float Bs[BK][BN];

    int tid = threadIdx.x;

    // A-load mapping: 2 float4 per thread along K
    const float* arow[2];
    int am[2], ak4[2];
    bool avalid[2];
    #pragma unroll
    for (int it = 0; it < 2; it++) {
        int idx = tid + it * 256;
        int m = idx >> 2, k4 = idx & 3;
        am[it] = m; ak4[it] = k4;
        int mg = m0 + m;
        avalid[it] = (mg < cnt);
        int p = off + (avalid[it] ? mg : 0);
        if (STAGE == 1) {
            int token = g_rows[p] >> 1;
            arow[it] = Xin + (size_t)token * K;
        } else {
            arow[it] = &g_hidden[(size_t)p * K];
        }
    }

    int tm = (tid >> 4) << 3;
    int tn = (tid & 15) << 3;

    float acc[8][8];
    #pragma unroll
    for (int i = 0; i < 8; i++)
        #pragma unroll
        for (int j = 0; j < 8; j++) acc[i][j] = 0.f;

    for (int k0 = 0; k0 < K; k0 += BK) {
        #pragma unroll
        for (int it = 0; it < 2; it++) {
            float4 v = make_float4(0.f, 0.f, 0.f, 0.f);
            if (avalid[it])
                v = *(const float4*)(arow[it] + k0 + ak4[it] * 4);
            As[ak4[it] * 4 + 0][am[it]] = v.x;
            As[ak4[it] * 4 + 1][am[it]] = v.y;
            As[ak4[it] * 4 + 2][am[it]] = v.z;
            As[ak4[it] * 4 + 3][am[it]] = v.w;
        }
        #pragma unroll
        for (int it = 0; it < 2; it++) {
            int idx = tid + it * 256;
            int kk = idx >> 5, nn = (idx & 31) << 2;
            *(float4*)&Bs[kk][nn] =
                *(const float4*)(B + (size_t)(k0 + kk) * NC + nn);
        }
        __syncthreads();

        #pragma unroll
        for (int kk = 0; kk < BK; kk++) {
            float a[8], b[8];
            *(float4*)&a[0] = *(const float4*)&As[kk][tm];
            *(float4*)&a[4] = *(const float4*)&As[kk][tm + 4];
            *(float4*)&b[0] = *(const float4*)&Bs[kk][tn];
            *(float4*)&b[4] = *(const float4*)&Bs[kk][tn + 4];
            #pragma unroll
            for (int i = 0; i < 8; i++)
                #pragma unroll
                for (int j = 0; j < 8; j++)
                    acc[i][j] += a[i] * b[j];
        }
        __syncthreads();
    }

    float bv[8];
    *(float4*)&bv[0] = *(const float4*)&bias[tn];
    *(float4*)&bv[4] = *(const float4*)&bias[tn + 4];

    #pragma unroll
    for (int i = 0; i < 8; i++) {
        int mg = m0 + tm + i;
        if (mg >= cnt) continue;
        int p = off + mg;
        float* dst;
        if (STAGE == 1) {
            dst = &g_hidden[(size_t)p * NC + n0 + tn];
        } else {
            int dr = g_rows[p];
            dst = &g_ybuf[(size_t)dr * NC + n0 + tn];
        }
        float o[8];
        #pragma unroll
        for (int j = 0; j < 8; j++) {
            float v = acc[i][j] + bv[j];
            if (STAGE == 1)
                v = 0.5f * v * (1.0f + erff(v * 0.70710678118654752f));
            o[j] = v;
        }
        *(float4*)dst       = *(float4*)&o[0];
        *(float4*)(dst + 4) = *(float4*)&o[4];
    }
}

// ---------------------------------------------------------------- combine
__global__ void combine_kernel(float* __restrict__ out, int N, int Dq) {
    int id = blockIdx.x * blockDim.x + threadIdx.x;
    if (id >= N * Dq) return;
    int n = id / Dq, d4 = id % Dq;
    float w0 = g_tkw[n * 2 + 0];
    float w1 = g_tkw[n * 2 + 1];
    const float4* y0 = (const float4*)&g_ybuf[(size_t)(n * 2 + 0) * Dq * 4];
    const float4* y1 = (const float4*)&g_ybuf[(size_t)(n * 2 + 1) * Dq * 4];
    float4 a = y0[d4], b = y1[d4];
    float4 r;
    r.x = w0 * a.x + w1 * b.x;
    r.y = w0 * a.y + w1 * b.y;
    r.z = w0 * a.z + w1 * b.z;
    r.w = w0 * a.w + w1 * b.w;
    ((float4*)out)[id] = r;
}

// ---------------------------------------------------------------- launch
extern "C" void kernel_launch(void* const* d_in, const int* in_sizes, int n_in,
                              void* d_out, int out_size) {
    const float* x  = (const float*)d_in[0];   // [B,T,D]
    const float* gw = (const float*)d_in[1];   // [D,E]
    const float* w1 = (const float*)d_in[2];   // [E,D,H]
    const float* b1 = (const float*)d_in[3];   // [E,H]
    const float* w2 = (const float*)d_in[4];   // [E,H,D]
    const float* b2 = (const float*)d_in[5];   // [E,D]

    long s2 = in_sizes[2], s3 = in_sizes[3], s5 = in_sizes[5];
    int D = (int)(s2 / s3);       // E*D*H / (E*H)
    int E = (int)(s5 / D);
    int H = (int)(s3 / E);
    int N = (int)(in_sizes[0] / D);

    init_kernel<<<1, 32>>>(E);
    router_kernel<<<N, 128>>>(x, gw, D, E);
    scan_kernel<<<1, 32>>>(E);
    scatter_kernel<<<(N + 255) / 256, 256>>>(N);

    int MT = (2 * N + 127) / 128;   // worst-case M tiles per expert
    dim3 g1(H / 128, MT, E);
    gemm_kernel<1><<<g1, 256>>>(x, w1, b1, D, H);
    dim3 g2(D / 128, MT, E);
    gemm_kernel<2><<<g2, 256>>>(x, w2, b2, H, D);

    int Dq = D / 4;
    combine_kernel<<<(N * Dq + 255) / 256, 256>>>((float*)d_out, N, Dq);
}